// round 1
// baseline (speedup 1.0000x reference)
#include <cuda_runtime.h>
#include <cstdint>

#define DK 512          // inner feature dim (K per half) — all layers have K=512
#define MAXN 10048
#define MAXE 161000

// ---------------- scratch (static __device__ globals; no allocation) --------
__device__ int   g_deg[MAXN];
__device__ int   g_rowptr[MAXN + 1];
__device__ int   g_cursor[MAXN];
__device__ int   g_csr[MAXE];
__device__ float g_invdeg[MAXN];
__device__ float g_agg[(size_t)MAXN * DK];
__device__ float g_h1 [(size_t)MAXN * DK];
__device__ float g_h2 [(size_t)MAXN * DK];

// ---------------- CSR build -------------------------------------------------
__global__ void k_zero_deg(int n) {
    int i = blockIdx.x * blockDim.x + threadIdx.x;
    if (i < n) g_deg[i] = 0;
}

__global__ void k_deg(const int* __restrict__ ei, int E) {
    int e = blockIdx.x * blockDim.x + threadIdx.x;
    if (e < E) atomicAdd(&g_deg[ei[E + e]], 1);
}

// Single-block exclusive scan (Hillis-Steele per 1024-chunk with carry).
__global__ void k_scan(int n) {
    __shared__ int s[1024];
    __shared__ int s_carry;
    int t = threadIdx.x;
    if (t == 0) s_carry = 0;
    __syncthreads();
    for (int base = 0; base < n; base += 1024) {
        int idx = base + t;
        int v = (idx < n) ? g_deg[idx] : 0;
        s[t] = v;
        __syncthreads();
        for (int off = 1; off < 1024; off <<= 1) {
            int add = (t >= off) ? s[t - off] : 0;
            __syncthreads();
            s[t] += add;
            __syncthreads();
        }
        int carry = s_carry;            // uniform (last write sync'd)
        if (idx < n) {
            g_rowptr[idx] = carry + s[t] - v;   // exclusive
            g_invdeg[idx] = 1.0f / (float)max(v, 1);
            g_cursor[idx] = 0;
        }
        __syncthreads();
        if (t == 0) s_carry = carry + s[1023];
        __syncthreads();
    }
    if (t == 0) g_rowptr[n] = s_carry;
}

__global__ void k_fill(const int* __restrict__ ei, int E) {
    int e = blockIdx.x * blockDim.x + threadIdx.x;
    if (e >= E) return;
    int d = ei[E + e];
    int pos = atomicAdd(&g_cursor[d], 1);
    g_csr[g_rowptr[d] + pos] = ei[e];   // src
}

// ---------------- aggregation: one block per dst node ----------------------
// 128 threads * float4 = 512 floats per row. Sums neighbor rows, scales by
// 1/max(deg,1), writes the already-normalized aggregate.
__global__ void k_aggregate(const float* __restrict__ x, float* __restrict__ agg, int n) {
    int dst = blockIdx.x;
    if (dst >= n) return;
    int beg = g_rowptr[dst], end = g_rowptr[dst + 1];
    int t = threadIdx.x;
    float4 acc = make_float4(0.f, 0.f, 0.f, 0.f);
    for (int e = beg; e < end; e++) {
        const float4* xr = reinterpret_cast<const float4*>(x + (size_t)g_csr[e] * DK);
        float4 v = xr[t];
        acc.x += v.x; acc.y += v.y; acc.z += v.z; acc.w += v.w;
    }
    float s = g_invdeg[dst];
    acc.x *= s; acc.y *= s; acc.z *= s; acc.w *= s;
    reinterpret_cast<float4*>(agg + (size_t)dst * DK)[t] = acc;
}

// ---------------- fused dual-GEMM + bias + BN + ReLU ------------------------
// out[i,j] = act( agg[i,:] @ Wl[:,j] + x[i,:] @ Wr[:,j] + b[j] )
// Single K loop over 2*DK: first half reads (agg, Wl), second half (x, Wr).
#define BM 128
#define BN 128
#define BK 8

__global__ __launch_bounds__(256)
void k_gemm_fused(const float* __restrict__ Aagg, const float* __restrict__ Ax,
                  const float* __restrict__ Wl,   const float* __restrict__ Wr,
                  const float* __restrict__ bias,
                  const float* __restrict__ gamma, const float* __restrict__ beta,
                  const float* __restrict__ mean,  const float* __restrict__ var,
                  float* __restrict__ out, int N, int Hdim, int bnrelu)
{
    __shared__ float As[BK][BM];
    __shared__ float Bs[BK][BN];

    const int t    = threadIdx.x;
    const int row0 = blockIdx.x * BM;
    const int col0 = blockIdx.y * BN;

    const int a_row = t >> 1;          // 0..127
    const int a_k4  = (t & 1) * 4;     // 0 or 4
    const int b_k   = t >> 5;          // 0..7
    const int b_c   = (t & 31) * 4;    // 0..124
    const int ty    = t >> 4;          // 0..15 -> 8 rows each
    const int tx    = t & 15;          // 0..15 -> 8 cols each

    float acc[8][8];
#pragma unroll
    for (int i = 0; i < 8; i++)
#pragma unroll
        for (int j = 0; j < 8; j++) acc[i][j] = 0.f;

    for (int kt = 0; kt < 2 * DK; kt += BK) {
        const float* A = (kt < DK) ? Aagg : Ax;
        const float* B = (kt < DK) ? Wl   : Wr;
        const int    kk = kt & (DK - 1);

        // A tile: 128 rows x 8 k, stored transposed As[k][row]
        float4 av = make_float4(0.f, 0.f, 0.f, 0.f);
        int gr = row0 + a_row;
        if (gr < N)
            av = *reinterpret_cast<const float4*>(A + (size_t)gr * DK + kk + a_k4);
        As[a_k4 + 0][a_row] = av.x;
        As[a_k4 + 1][a_row] = av.y;
        As[a_k4 + 2][a_row] = av.z;
        As[a_k4 + 3][a_row] = av.w;

        // B tile: 8 k-rows x 128 cols (K,H multiples of tile — no guard)
        float4 bv = *reinterpret_cast<const float4*>(B + (size_t)(kk + b_k) * Hdim + col0 + b_c);
        *reinterpret_cast<float4*>(&Bs[b_k][b_c]) = bv;

        __syncthreads();

#pragma unroll
        for (int k = 0; k < BK; k++) {
            float a[8], b[8];
            *(float4*)&a[0] = *(const float4*)&As[k][ty * 8];
            *(float4*)&a[4] = *(const float4*)&As[k][ty * 8 + 4];
            *(float4*)&b[0] = *(const float4*)&Bs[k][tx * 8];
            *(float4*)&b[4] = *(const float4*)&Bs[k][tx * 8 + 4];
#pragma unroll
            for (int i = 0; i < 8; i++)
#pragma unroll
                for (int j = 0; j < 8; j++)
                    acc[i][j] += a[i] * b[j];
        }
        __syncthreads();
    }

    // Epilogue: fold bias + BN into per-column scale/shift.
    float sc[8], sh[8];
#pragma unroll
    for (int j = 0; j < 8; j++) {
        int c = col0 + tx * 8 + j;
        float bb = bias[c];
        if (bnrelu) {
            float s = gamma[c] * rsqrtf(var[c] + 1e-5f);
            sc[j] = s;
            sh[j] = (bb - mean[c]) * s + beta[c];
        } else {
            sc[j] = 1.f;
            sh[j] = bb;
        }
    }
#pragma unroll
    for (int i = 0; i < 8; i++) {
        int r = row0 + ty * 8 + i;
        if (r < N) {
#pragma unroll
            for (int j = 0; j < 8; j++) {
                float v = acc[i][j] * sc[j] + sh[j];
                if (bnrelu) v = fmaxf(v, 0.f);
                out[(size_t)r * Hdim + col0 + tx * 8 + j] = v;
            }
        }
    }
}

// ---------------- launch ----------------------------------------------------
extern "C" void kernel_launch(void* const* d_in, const int* in_sizes, int n_in,
                              void* d_out, int out_size)
{
    const float* x      = (const float*)d_in[0];
    const int*   ei     = (const int*)  d_in[1];
    const float* w_l1   = (const float*)d_in[2];
    const float* b1     = (const float*)d_in[3];
    const float* w_r1   = (const float*)d_in[4];
    const float* bn1_g  = (const float*)d_in[5];
    const float* bn1_b  = (const float*)d_in[6];
    const float* bn1_m  = (const float*)d_in[7];
    const float* bn1_v  = (const float*)d_in[8];
    const float* w_l2   = (const float*)d_in[9];
    const float* b2     = (const float*)d_in[10];
    const float* w_r2   = (const float*)d_in[11];
    const float* bn2_g  = (const float*)d_in[12];
    const float* bn2_b  = (const float*)d_in[13];
    const float* bn2_m  = (const float*)d_in[14];
    const float* bn2_v  = (const float*)d_in[15];
    const float* w_l3   = (const float*)d_in[16];
    const float* b3     = (const float*)d_in[17];
    const float* w_r3   = (const float*)d_in[18];
    float* out = (float*)d_out;

    const int N = in_sizes[0] / DK;
    const int E = in_sizes[1] / 2;
    const int O = out_size / N;   // 256

    float *agg, *h1, *h2;
    cudaGetSymbolAddress((void**)&agg, g_agg);
    cudaGetSymbolAddress((void**)&h1,  g_h1);
    cudaGetSymbolAddress((void**)&h2,  g_h2);

    // CSR build (reused by all three layers)
    k_zero_deg<<<(N + 255) / 256, 256>>>(N);
    k_deg     <<<(E + 255) / 256, 256>>>(ei, E);
    k_scan    <<<1, 1024>>>(N);
    k_fill    <<<(E + 255) / 256, 256>>>(ei, E);

    dim3 gH((N + BM - 1) / BM, DK / BN);  // H = 512
    dim3 gO((N + BM - 1) / BM, O  / BN);  // O = 256

    // Layer 1
    k_aggregate<<<N, 128>>>(x, agg, N);
    k_gemm_fused<<<gH, 256>>>(agg, x, w_l1, w_r1, b1,
                              bn1_g, bn1_b, bn1_m, bn1_v, h1, N, DK, 1);
    // Layer 2
    k_aggregate<<<N, 128>>>(h1, agg, N);
    k_gemm_fused<<<gH, 256>>>(agg, h1, w_l2, w_r2, b2,
                              bn2_g, bn2_b, bn2_m, bn2_v, h2, N, DK, 1);
    // Layer 3 (no BN/ReLU)
    k_aggregate<<<N, 128>>>(h2, agg, N);
    k_gemm_fused<<<gO, 256>>>(agg, h2, w_l3, w_r3, b3,
                              b3, b3, b3, b3, out, N, O, 0);
}

// round 3
// speedup vs baseline: 3.0427x; 3.0427x over previous
#include <cuda_runtime.h>
#include <cstdint>

#define DK 512
#define MAXN 10048
#define MAXE 161000

// ---------------- scratch ----------------------------------------------------
__device__ int   g_deg[MAXN];
__device__ int   g_rowptr[MAXN + 1];
__device__ int   g_cursor[MAXN];
__device__ int   g_csr[MAXE];
__device__ float g_invdeg[MAXN];
__device__ float g_agg[(size_t)MAXN * DK];
__device__ float g_h1 [(size_t)MAXN * DK];
__device__ float g_h2 [(size_t)MAXN * DK];
// transposed tf32-rounded weights: wlt1,wrt1,wlt2,wrt2 (512x512), wlt3,wrt3 (256x512)
__device__ float g_wt[4 * 512 * 512 + 2 * 256 * 512];

// ---------------- helpers ------------------------------------------------
__device__ __forceinline__ uint32_t smem_u32(const void* p) {
    uint32_t a;
    asm("{ .reg .u64 t; cvta.to.shared.u64 t, %1; cvt.u32.u64 %0, t; }" : "=r"(a) : "l"(p));
    return a;
}
__device__ __forceinline__ float tf32_rna(float x) {
    uint32_t r;
    asm("cvt.rna.tf32.f32 %0, %1;" : "=r"(r) : "f"(x));
    return __uint_as_float(r);
}
__device__ __forceinline__ void ldsm_x4(uint32_t* r, uint32_t addr) {
    asm volatile("ldmatrix.sync.aligned.m8n8.x4.shared.b16 {%0,%1,%2,%3}, [%4];"
                 : "=r"(r[0]), "=r"(r[1]), "=r"(r[2]), "=r"(r[3]) : "r"(addr));
}
__device__ __forceinline__ void mma_tf32(float* d, const uint32_t* a, const uint32_t* b) {
    asm volatile("mma.sync.aligned.m16n8k8.row.col.f32.tf32.tf32.f32 "
                 "{%0,%1,%2,%3}, {%4,%5,%6,%7}, {%8,%9}, {%0,%1,%2,%3};"
                 : "+f"(d[0]), "+f"(d[1]), "+f"(d[2]), "+f"(d[3])
                 : "r"(a[0]), "r"(a[1]), "r"(a[2]), "r"(a[3]), "r"(b[0]), "r"(b[1]));
}

// ---------------- CSR build --------------------------------------------------
__global__ void k_zero_deg(int n) {
    int i = blockIdx.x * blockDim.x + threadIdx.x;
    if (i < n) g_deg[i] = 0;
}
__global__ void k_deg(const int* __restrict__ ei, int E) {
    int e = blockIdx.x * blockDim.x + threadIdx.x;
    if (e < E) atomicAdd(&g_deg[ei[E + e]], 1);
}
__global__ void k_scan(int n) {
    __shared__ int s[1024];
    __shared__ int s_carry;
    int t = threadIdx.x;
    if (t == 0) s_carry = 0;
    __syncthreads();
    for (int base = 0; base < n; base += 1024) {
        int idx = base + t;
        int v = (idx < n) ? g_deg[idx] : 0;
        s[t] = v;
        __syncthreads();
        for (int off = 1; off < 1024; off <<= 1) {
            int add = (t >= off) ? s[t - off] : 0;
            __syncthreads();
            s[t] += add;
            __syncthreads();
        }
        int carry = s_carry;
        if (idx < n) {
            g_rowptr[idx] = carry + s[t] - v;
            g_invdeg[idx] = 1.0f / (float)max(v, 1);
            g_cursor[idx] = 0;
        }
        __syncthreads();
        if (t == 0) s_carry = carry + s[1023];
        __syncthreads();
    }
    if (t == 0) g_rowptr[n] = s_carry;
}
__global__ void k_fill(const int* __restrict__ ei, int E) {
    int e = blockIdx.x * blockDim.x + threadIdx.x;
    if (e >= E) return;
    int d = ei[E + e];
    int pos = atomicAdd(&g_cursor[d], 1);
    g_csr[g_rowptr[d] + pos] = ei[e];
}

// ---------------- weight transpose + tf32 round ------------------------------
__global__ void k_transpose_tf32(const float* __restrict__ W, float* __restrict__ WT,
                                 int K, int H) {
    __shared__ float tile[32][33];
    int k0 = blockIdx.x * 32, h0 = blockIdx.y * 32;
    int tx = threadIdx.x, ty = threadIdx.y;   // 32 x 8
#pragma unroll
    for (int i = 0; i < 32; i += 8)
        tile[ty + i][tx] = W[(size_t)(k0 + ty + i) * H + h0 + tx];
    __syncthreads();
#pragma unroll
    for (int i = 0; i < 32; i += 8)
        WT[(size_t)(h0 + ty + i) * K + k0 + tx] = tf32_rna(tile[tx][ty + i]);
}

// ---------------- aggregation ------------------------------------------------
__global__ void k_aggregate(const float* __restrict__ x, float* __restrict__ agg, int n) {
    int dst = blockIdx.x;
    if (dst >= n) return;
    int beg = g_rowptr[dst], end = g_rowptr[dst + 1];
    int t = threadIdx.x;
    float4 acc = make_float4(0.f, 0.f, 0.f, 0.f);
    for (int e = beg; e < end; e++) {
        const float4* xr = reinterpret_cast<const float4*>(x + (size_t)g_csr[e] * DK);
        float4 v = xr[t];
        acc.x += v.x; acc.y += v.y; acc.z += v.z; acc.w += v.w;
    }
    float s = g_invdeg[dst];
    acc.x *= s; acc.y *= s; acc.z *= s; acc.w *= s;
    reinterpret_cast<float4*>(agg + (size_t)dst * DK)[t] = acc;
}

// ---------------- tf32 mma.sync dual-GEMM + bias/BN/ReLU ---------------------
// out[m, n] = act( sum_k agg[m,k] WlT[n,k] + sum_k xin[m,k] WrT[n,k] + b[n] )
// 128x128 tile, BK=32, 32 chunks over 2*512, double-buffered swizzled smem.
#define NCHUNK 32
#define GSMEM  (2 * 32768)   // 2 buffers x (16KB A + 16KB B)

__global__ __launch_bounds__(256, 1)
void k_gemm_mma(const float* __restrict__ Aagg, const float* __restrict__ Ax,
                const float* __restrict__ WlT,  const float* __restrict__ WrT,
                const float* __restrict__ bias,
                const float* __restrict__ gamma, const float* __restrict__ beta,
                const float* __restrict__ mean,  const float* __restrict__ var,
                float* __restrict__ out, int N, int Hdim, int bnrelu)
{
    extern __shared__ char smem[];
    const uint32_t sb = smem_u32(smem);
    const int t    = threadIdx.x;
    const int lane = t & 31, wid = t >> 5;
    const int warp_m = wid & 3;          // 4 warps over 128 rows (32 each)
    const int warp_n = wid >> 2;         // 2 warps over 128 cols (64 each)
    const int row0 = blockIdx.x * 128;
    const int col0 = blockIdx.y * 128;

    // ldmatrix per-thread addressing (A: mat&1 = row-group, mat>>1 = k-half;
    //                                 B: mat&1 = k-half,   mat>>1 = row-group)
    const int rin  = lane & 7;
    const int aGrp = (lane >> 3) & 1, aKhi = (lane >> 4) & 1;
    const int rA0  = warp_m * 32 + aGrp * 8 + rin;         // mt = 0
    const uint32_t aO0 = (uint32_t)rA0 * 128;
    const uint32_t aO1 = (uint32_t)(rA0 + 16) * 128;
    const uint32_t aRm = (uint32_t)(rA0 & 7);
    const int bGrp = (lane >> 4) & 1, bKhi = (lane >> 3) & 1;
    const int rB   = warp_n * 64 + bGrp * 8 + rin;
    const uint32_t bRm = (uint32_t)(rB & 7);               // +p*16 keeps &7
    uint32_t bO[4];
#pragma unroll
    for (int p = 0; p < 4; p++) bO[p] = (uint32_t)(rB + p * 16) * 128;

    float d[2][8][4];
#pragma unroll
    for (int mt = 0; mt < 2; mt++)
#pragma unroll
        for (int nt = 0; nt < 8; nt++)
#pragma unroll
            for (int q = 0; q < 4; q++) d[mt][nt][q] = 0.f;

    float4 pa[4], pb[4];

    // ---- prefetch chunk 0
    {
        const float* As = Aagg;
        const float* Bs = WlT;
#pragma unroll
        for (int i = 0; i < 4; i++) {
            int idx = t + i * 256, row = idx >> 3, f4 = idx & 7;
            int gr = min(row0 + row, N - 1);
            pa[i] = *reinterpret_cast<const float4*>(As + (size_t)gr * DK + f4 * 4);
            pb[i] = *reinterpret_cast<const float4*>(Bs + (size_t)(col0 + row) * DK + f4 * 4);
        }
    }
    // ---- STS chunk 0 into buf 0
#pragma unroll
    for (int i = 0; i < 4; i++) {
        int idx = t + i * 256, row = idx >> 3, f4 = idx & 7;
        uint32_t off = (uint32_t)row * 128 + (uint32_t)((f4 ^ (row & 7)) << 4);
        float4 v = pa[i];
        v.x = tf32_rna(v.x); v.y = tf32_rna(v.y); v.z = tf32_rna(v.z); v.w = tf32_rna(v.w);
        *reinterpret_cast<float4*>(smem + off) = v;
        *reinterpret_cast<float4*>(smem + 16384 + off) = pb[i];
    }
    __syncthreads();

    for (int c = 0; c < NCHUNK; c++) {
        // prefetch c+1
        if (c < NCHUNK - 1) {
            const int cc = c + 1;
            const float* As = (cc < 16) ? Aagg : Ax;
            const float* Bs = (cc < 16) ? WlT  : WrT;
            const int kk = (cc & 15) * 32;
#pragma unroll
            for (int i = 0; i < 4; i++) {
                int idx = t + i * 256, row = idx >> 3, f4 = idx & 7;
                int gr = min(row0 + row, N - 1);
                pa[i] = *reinterpret_cast<const float4*>(As + (size_t)gr * DK + kk + f4 * 4);
                pb[i] = *reinterpret_cast<const float4*>(Bs + (size_t)(col0 + row) * DK + kk + f4 * 4);
            }
        }

        // compute chunk c from buf (c&1)
        const uint32_t Ab = sb + (uint32_t)(c & 1) * 32768;
        const uint32_t Bb = Ab + 16384;
#pragma unroll
        for (int ks = 0; ks < 4; ks++) {
            uint32_t a[2][4], b[4][4];
            uint32_t ca = (((uint32_t)(ks * 2 + aKhi) ^ aRm) << 4);
            ldsm_x4(a[0], Ab + aO0 + ca);
            ldsm_x4(a[1], Ab + aO1 + ca);
            uint32_t cb = (((uint32_t)(ks * 2 + bKhi) ^ bRm) << 4);
#pragma unroll
            for (int p = 0; p < 4; p++) ldsm_x4(b[p], Bb + bO[p] + cb);
#pragma unroll
            for (int mt = 0; mt < 2; mt++)
#pragma unroll
                for (int p = 0; p < 4; p++) {
                    mma_tf32(d[mt][p * 2 + 0], a[mt], &b[p][0]);
                    mma_tf32(d[mt][p * 2 + 1], a[mt], &b[p][2]);
                }
        }

        // STS c+1 into buf ((c+1)&1)  — safe: that buffer was last read in c-1
        if (c < NCHUNK - 1) {
            char* dst = smem + ((c + 1) & 1) * 32768;
#pragma unroll
            for (int i = 0; i < 4; i++) {
                int idx = t + i * 256, row = idx >> 3, f4 = idx & 7;
                uint32_t off = (uint32_t)row * 128 + (uint32_t)((f4 ^ (row & 7)) << 4);
                float4 v = pa[i];
                v.x = tf32_rna(v.x); v.y = tf32_rna(v.y); v.z = tf32_rna(v.z); v.w = tf32_rna(v.w);
                *reinterpret_cast<float4*>(dst + off) = v;
                *reinterpret_cast<float4*>(dst + 16384 + off) = pb[i];
            }
        }
        __syncthreads();
    }

    // ---- epilogue
    const int g  = lane >> 2;
    const int cp = (lane & 3) * 2;
#pragma unroll
    for (int nt = 0; nt < 8; nt++) {
        const int gc = col0 + warp_n * 64 + nt * 8 + cp;
        float s0 = 1.f, s1 = 1.f, h0 = bias[gc], h1 = bias[gc + 1];
        if (bnrelu) {
            float r0 = gamma[gc]     * rsqrtf(var[gc]     + 1e-5f);
            float r1 = gamma[gc + 1] * rsqrtf(var[gc + 1] + 1e-5f);
            h0 = (h0 - mean[gc])     * r0 + beta[gc];
            h1 = (h1 - mean[gc + 1]) * r1 + beta[gc + 1];
            s0 = r0; s1 = r1;
        }
#pragma unroll
        for (int mt = 0; mt < 2; mt++) {
            const int r_lo = row0 + warp_m * 32 + mt * 16 + g;
            const int r_hi = r_lo + 8;
            float v0 = d[mt][nt][0] * s0 + h0;
            float v1 = d[mt][nt][1] * s1 + h1;
            float v2 = d[mt][nt][2] * s0 + h0;
            float v3 = d[mt][nt][3] * s1 + h1;
            if (bnrelu) {
                v0 = fmaxf(v0, 0.f); v1 = fmaxf(v1, 0.f);
                v2 = fmaxf(v2, 0.f); v3 = fmaxf(v3, 0.f);
            }
            if (r_lo < N) *reinterpret_cast<float2*>(out + (size_t)r_lo * Hdim + gc) = make_float2(v0, v1);
            if (r_hi < N) *reinterpret_cast<float2*>(out + (size_t)r_hi * Hdim + gc) = make_float2(v2, v3);
        }
    }
}

// ---------------- launch ------------------------------------------------------
extern "C" void kernel_launch(void* const* d_in, const int* in_sizes, int n_in,
                              void* d_out, int out_size)
{
    const float* x     = (const float*)d_in[0];
    const int*   ei    = (const int*)  d_in[1];
    const float* w_l1  = (const float*)d_in[2];
    const float* b1    = (const float*)d_in[3];
    const float* w_r1  = (const float*)d_in[4];
    const float* bn1_g = (const float*)d_in[5];
    const float* bn1_b = (const float*)d_in[6];
    const float* bn1_m = (const float*)d_in[7];
    const float* bn1_v = (const float*)d_in[8];
    const float* w_l2  = (const float*)d_in[9];
    const float* b2    = (const float*)d_in[10];
    const float* w_r2  = (const float*)d_in[11];
    const float* bn2_g = (const float*)d_in[12];
    const float* bn2_b = (const float*)d_in[13];
    const float* bn2_m = (const float*)d_in[14];
    const float* bn2_v = (const float*)d_in[15];
    const float* w_l3  = (const float*)d_in[16];
    const float* b3    = (const float*)d_in[17];
    const float* w_r3  = (const float*)d_in[18];
    float* out = (float*)d_out;

    const int N = in_sizes[0] / DK;
    const int E = in_sizes[1] / 2;
    const int O = out_size / N;   // 256

    float *agg, *h1, *h2, *wt;
    cudaGetSymbolAddress((void**)&agg, g_agg);
    cudaGetSymbolAddress((void**)&h1,  g_h1);
    cudaGetSymbolAddress((void**)&h2,  g_h2);
    cudaGetSymbolAddress((void**)&wt,  g_wt);
    float* wlt1 = wt;
    float* wrt1 = wt + 512 * 512;
    float* wlt2 = wt + 2 * 512 * 512;
    float* wrt2 = wt + 3 * 512 * 512;
    float* wlt3 = wt + 4 * 512 * 512;
    float* wrt3 = wt + 4 * 512 * 512 + 256 * 512;

    cudaFuncSetAttribute(k_gemm_mma, cudaFuncAttributeMaxDynamicSharedMemorySize, GSMEM);

    // CSR build
    k_zero_deg<<<(N + 255) / 256, 256>>>(N);
    k_deg     <<<(E + 255) / 256, 256>>>(ei, E);
    k_scan    <<<1, 1024>>>(N);
    k_fill    <<<(E + 255) / 256, 256>>>(ei, E);

    // weight transposes (tf32-rounded)
    dim3 tb(32, 8);
    k_transpose_tf32<<<dim3(16, 16), tb>>>(w_l1, wlt1, 512, 512);
    k_transpose_tf32<<<dim3(16, 16), tb>>>(w_r1, wrt1, 512, 512);
    k_transpose_tf32<<<dim3(16, 16), tb>>>(w_l2, wlt2, 512, 512);
    k_transpose_tf32<<<dim3(16, 16), tb>>>(w_r2, wrt2, 512, 512);
    k_transpose_tf32<<<dim3(16, 8),  tb>>>(w_l3, wlt3, 512, 256);
    k_transpose_tf32<<<dim3(16, 8),  tb>>>(w_r3, wrt3, 512, 256);

    const int mt = (N + 127) / 128;
    dim3 gH(mt, 512 / 128);
    dim3 gO(mt, O / 128);

    // Layer 1
    k_aggregate<<<N, 128>>>(x, agg, N);
    k_gemm_mma<<<gH, 256, GSMEM>>>(agg, x, wlt1, wrt1, b1,
                                   bn1_g, bn1_b, bn1_m, bn1_v, h1, N, 512, 1);
    // Layer 2
    k_aggregate<<<N, 128>>>(h1, agg, N);
    k_gemm_mma<<<gH, 256, GSMEM>>>(agg, h1, wlt2, wrt2, b2,
                                   bn2_g, bn2_b, bn2_m, bn2_v, h2, N, 512, 1);
    // Layer 3 (no BN/ReLU)
    k_aggregate<<<N, 128>>>(h2, agg, N);
    k_gemm_mma<<<gO, 256, GSMEM>>>(agg, h2, wlt3, wrt3, b3,
                                   b3, b3, b3, b3, out, N, O, 0);
}

// round 4
// speedup vs baseline: 4.0064x; 1.3167x over previous
#include <cuda_runtime.h>
#include <cstdint>

#define DK 512
#define MAXN 10048
#define MAXE 161000

// ---------------- scratch ----------------------------------------------------
__device__ int   g_deg[MAXN];
__device__ int   g_rowptr[MAXN + 1];
__device__ int   g_cursor[MAXN];
__device__ int   g_csr[MAXE];
__device__ float g_invdeg[MAXN];
__device__ float g_xt [(size_t)MAXN * DK];   // tf32-rounded copy of x
__device__ float g_agg[(size_t)MAXN * DK];
__device__ float g_h1 [(size_t)MAXN * DK];
__device__ float g_h2 [(size_t)MAXN * DK];
__device__ float g_wt[4 * 512 * 512 + 2 * 256 * 512];

// ---------------- helpers ------------------------------------------------
__device__ __forceinline__ uint32_t smem_u32(const void* p) {
    uint32_t a;
    asm("{ .reg .u64 t; cvta.to.shared.u64 t, %1; cvt.u32.u64 %0, t; }" : "=r"(a) : "l"(p));
    return a;
}
__device__ __forceinline__ float tf32_rna(float x) {
    uint32_t r;
    asm("cvt.rna.tf32.f32 %0, %1;" : "=r"(r) : "f"(x));
    return __uint_as_float(r);
}
__device__ __forceinline__ void ldsm_x4(uint32_t* r, uint32_t addr) {
    asm volatile("ldmatrix.sync.aligned.m8n8.x4.shared.b16 {%0,%1,%2,%3}, [%4];"
                 : "=r"(r[0]), "=r"(r[1]), "=r"(r[2]), "=r"(r[3]) : "r"(addr));
}
__device__ __forceinline__ void mma_tf32(float* d, const uint32_t* a, const uint32_t* b) {
    asm volatile("mma.sync.aligned.m16n8k8.row.col.f32.tf32.tf32.f32 "
                 "{%0,%1,%2,%3}, {%4,%5,%6,%7}, {%8,%9}, {%0,%1,%2,%3};"
                 : "+f"(d[0]), "+f"(d[1]), "+f"(d[2]), "+f"(d[3])
                 : "r"(a[0]), "r"(a[1]), "r"(a[2]), "r"(a[3]), "r"(b[0]), "r"(b[1]));
}
__device__ __forceinline__ void cp16(uint32_t dst, const void* src) {
    asm volatile("cp.async.cg.shared.global [%0], [%1], 16;" :: "r"(dst), "l"(src));
}
#define CP_COMMIT() asm volatile("cp.async.commit_group;" ::: "memory")
#define CP_WAIT1()  asm volatile("cp.async.wait_group 1;" ::: "memory")
#define CP_WAIT0()  asm volatile("cp.async.wait_group 0;" ::: "memory")

// ---------------- CSR build --------------------------------------------------
__global__ void k_zero_deg(int n) {
    int i = blockIdx.x * blockDim.x + threadIdx.x;
    if (i < n) g_deg[i] = 0;
}
__global__ void k_deg(const int* __restrict__ ei, int E) {
    int e = blockIdx.x * blockDim.x + threadIdx.x;
    if (e < E) atomicAdd(&g_deg[ei[E + e]], 1);
}
__global__ void k_scan(int n) {
    __shared__ int ws[32];
    __shared__ int s_carry;
    const int t = threadIdx.x, lane = t & 31, w = t >> 5;
    if (t == 0) s_carry = 0;
    __syncthreads();
    for (int base = 0; base < n; base += 1024) {
        int idx = base + t;
        int v = (idx < n) ? g_deg[idx] : 0;
        int sc = v;
#pragma unroll
        for (int o = 1; o < 32; o <<= 1) {
            int u = __shfl_up_sync(0xffffffffu, sc, o);
            if (lane >= o) sc += u;
        }
        if (lane == 31) ws[w] = sc;
        __syncthreads();
        if (w == 0) {
            int x2 = ws[lane];
#pragma unroll
            for (int o = 1; o < 32; o <<= 1) {
                int u = __shfl_up_sync(0xffffffffu, x2, o);
                if (lane >= o) x2 += u;
            }
            ws[lane] = x2;
        }
        __syncthreads();
        int carry = s_carry;
        int add = carry + (w ? ws[w - 1] : 0);
        if (idx < n) {
            g_rowptr[idx] = add + sc - v;
            g_invdeg[idx] = 1.0f / (float)max(v, 1);
            g_cursor[idx] = 0;
        }
        __syncthreads();
        if (t == 0) s_carry = carry + ws[31];
        __syncthreads();
    }
    if (t == 0) g_rowptr[n] = s_carry;
}
__global__ void k_fill(const int* __restrict__ ei, int E) {
    int e = blockIdx.x * blockDim.x + threadIdx.x;
    if (e >= E) return;
    int d = ei[E + e];
    int pos = atomicAdd(&g_cursor[d], 1);
    g_csr[g_rowptr[d] + pos] = ei[e];
}

// ---------------- tf32 rounding copy of x ------------------------------------
__global__ void k_round(const float* __restrict__ src, float* __restrict__ dst, int n4) {
    int i = blockIdx.x * blockDim.x + threadIdx.x;
    if (i >= n4) return;
    float4 v = reinterpret_cast<const float4*>(src)[i];
    v.x = tf32_rna(v.x); v.y = tf32_rna(v.y); v.z = tf32_rna(v.z); v.w = tf32_rna(v.w);
    reinterpret_cast<float4*>(dst)[i] = v;
}

// ---------------- merged weight transposes (tf32) ----------------------------
struct TP { const float* W; float* WT; int H; };
struct TP6 { TP m[6]; };
__global__ void k_transpose_all(TP6 tps) {
    const TP tp = tps.m[blockIdx.z];
    const int H = tp.H;
    int k0 = blockIdx.x * 32, h0 = blockIdx.y * 32;
    if (h0 >= H) return;
    __shared__ float tile[32][33];
    int tx = threadIdx.x, ty = threadIdx.y;   // 32 x 8
#pragma unroll
    for (int i = 0; i < 32; i += 8)
        tile[ty + i][tx] = tp.W[(size_t)(k0 + ty + i) * H + h0 + tx];
    __syncthreads();
#pragma unroll
    for (int i = 0; i < 32; i += 8)
        tp.WT[(size_t)(h0 + ty + i) * DK + k0 + tx] = tf32_rna(tile[tx][ty + i]);
}

// ---------------- aggregation (tf32-rounded output) ---------------------------
__global__ void k_aggregate(const float* __restrict__ x, float* __restrict__ agg, int n) {
    int dst = blockIdx.x;
    if (dst >= n) return;
    int beg = g_rowptr[dst], end = g_rowptr[dst + 1];
    int t = threadIdx.x;
    float4 acc = make_float4(0.f, 0.f, 0.f, 0.f);
    for (int e = beg; e < end; e++) {
        const float4* xr = reinterpret_cast<const float4*>(x + (size_t)g_csr[e] * DK);
        float4 v = xr[t];
        acc.x += v.x; acc.y += v.y; acc.z += v.z; acc.w += v.w;
    }
    float s = g_invdeg[dst];
    acc.x = tf32_rna(acc.x * s); acc.y = tf32_rna(acc.y * s);
    acc.z = tf32_rna(acc.z * s); acc.w = tf32_rna(acc.w * s);
    reinterpret_cast<float4*>(agg + (size_t)dst * DK)[t] = acc;
}

// ---------------- tf32 mma.sync dual-GEMM, cp.async 3-stage -------------------
// All A/B inputs pre-rounded to tf32. 128x128 tile, BK=32, 32 chunks.
#define NCHUNK 32
#define STAGES 3
#define GSMEM  (STAGES * 32768)

__global__ __launch_bounds__(256, 2)
void k_gemm_mma(const float* __restrict__ Aagg, const float* __restrict__ Ax,
                const float* __restrict__ WlT,  const float* __restrict__ WrT,
                const float* __restrict__ bias,
                const float* __restrict__ gamma, const float* __restrict__ beta,
                const float* __restrict__ mean,  const float* __restrict__ var,
                float* __restrict__ out, int N, int Hdim, int bnrelu)
{
    extern __shared__ char smem[];
    const uint32_t sb = smem_u32(smem);
    const int t    = threadIdx.x;
    const int lane = t & 31, wid = t >> 5;
    const int warp_m = wid & 3;
    const int warp_n = wid >> 2;
    const int row0 = blockIdx.x * 128;
    const int col0 = blockIdx.y * 128;

    // per-thread load coords (4 x 16B for A, 4 x 16B for B per stage)
    int lrow[4], lf4[4];
    uint32_t loff[4];
    const float* arow[4];
#pragma unroll
    for (int i = 0; i < 4; i++) {
        int idx = t + i * 256;
        lrow[i] = idx >> 3; lf4[i] = idx & 7;
        loff[i] = (uint32_t)lrow[i] * 128 + (uint32_t)((lf4[i] ^ (lrow[i] & 7)) << 4);
    }

    // ldmatrix addressing
    const int rin  = lane & 7;
    const int aGrp = (lane >> 3) & 1, aKhi = (lane >> 4) & 1;
    const int rA0  = warp_m * 32 + aGrp * 8 + rin;
    const uint32_t aO0 = (uint32_t)rA0 * 128;
    const uint32_t aO1 = (uint32_t)(rA0 + 16) * 128;
    const uint32_t aRm = (uint32_t)(rA0 & 7);
    const int bGrp = (lane >> 4) & 1, bKhi = (lane >> 3) & 1;
    const int rB   = warp_n * 64 + bGrp * 8 + rin;
    const uint32_t bRm = (uint32_t)(rB & 7);
    uint32_t bO[4];
#pragma unroll
    for (int p = 0; p < 4; p++) bO[p] = (uint32_t)(rB + p * 16) * 128;

    float d[2][8][4];
#pragma unroll
    for (int mt = 0; mt < 2; mt++)
#pragma unroll
        for (int nt = 0; nt < 8; nt++)
#pragma unroll
            for (int q = 0; q < 4; q++) d[mt][nt][q] = 0.f;

    // stage loader
    auto load_stage = [&](int c) {
        const float* As = (c < 16) ? Aagg : Ax;
        const float* Bs = (c < 16) ? WlT  : WrT;
        const int kk = (c & 15) * 32;
        const uint32_t base = sb + (uint32_t)(c % STAGES) * 32768;
#pragma unroll
        for (int i = 0; i < 4; i++) {
            int gr = min(row0 + lrow[i], N - 1);
            cp16(base + loff[i], As + (size_t)gr * DK + kk + lf4[i] * 4);
            cp16(base + 16384 + loff[i], Bs + (size_t)(col0 + lrow[i]) * DK + kk + lf4[i] * 4);
        }
        CP_COMMIT();
    };

    load_stage(0);
    load_stage(1);

    for (int c = 0; c < NCHUNK; c++) {
        if (c + 1 < NCHUNK) { CP_WAIT1(); } else { CP_WAIT0(); }
        __syncthreads();

        const uint32_t Ab = sb + (uint32_t)(c % STAGES) * 32768;
        const uint32_t Bb = Ab + 16384;
#pragma unroll
        for (int ks = 0; ks < 4; ks++) {
            uint32_t a[2][4], b[4][4];
            uint32_t ca = (((uint32_t)(ks * 2 + aKhi) ^ aRm) << 4);
            ldsm_x4(a[0], Ab + aO0 + ca);
            ldsm_x4(a[1], Ab + aO1 + ca);
            uint32_t cb = (((uint32_t)(ks * 2 + bKhi) ^ bRm) << 4);
#pragma unroll
            for (int p = 0; p < 4; p++) ldsm_x4(b[p], Bb + bO[p] + cb);
#pragma unroll
            for (int mt = 0; mt < 2; mt++)
#pragma unroll
                for (int p = 0; p < 4; p++) {
                    mma_tf32(d[mt][p * 2 + 0], a[mt], &b[p][0]);
                    mma_tf32(d[mt][p * 2 + 1], a[mt], &b[p][2]);
                }
        }
        if (c + 2 < NCHUNK) load_stage(c + 2);
    }

    // ---- epilogue
    const int g  = lane >> 2;
    const int cp = (lane & 3) * 2;
#pragma unroll
    for (int nt = 0; nt < 8; nt++) {
        const int gc = col0 + warp_n * 64 + nt * 8 + cp;
        float s0 = 1.f, s1 = 1.f, h0 = bias[gc], h1 = bias[gc + 1];
        if (bnrelu) {
            float r0 = gamma[gc]     * rsqrtf(var[gc]     + 1e-5f);
            float r1 = gamma[gc + 1] * rsqrtf(var[gc + 1] + 1e-5f);
            h0 = (h0 - mean[gc])     * r0 + beta[gc];
            h1 = (h1 - mean[gc + 1]) * r1 + beta[gc + 1];
            s0 = r0; s1 = r1;
        }
#pragma unroll
        for (int mt = 0; mt < 2; mt++) {
            const int r_lo = row0 + warp_m * 32 + mt * 16 + g;
            const int r_hi = r_lo + 8;
            float v0 = d[mt][nt][0] * s0 + h0;
            float v1 = d[mt][nt][1] * s1 + h1;
            float v2 = d[mt][nt][2] * s0 + h0;
            float v3 = d[mt][nt][3] * s1 + h1;
            if (bnrelu) {
                v0 = tf32_rna(fmaxf(v0, 0.f)); v1 = tf32_rna(fmaxf(v1, 0.f));
                v2 = tf32_rna(fmaxf(v2, 0.f)); v3 = tf32_rna(fmaxf(v3, 0.f));
            }
            if (r_lo < N) *reinterpret_cast<float2*>(out + (size_t)r_lo * Hdim + gc) = make_float2(v0, v1);
            if (r_hi < N) *reinterpret_cast<float2*>(out + (size_t)r_hi * Hdim + gc) = make_float2(v2, v3);
        }
    }
}

// ---------------- launch ------------------------------------------------------
extern "C" void kernel_launch(void* const* d_in, const int* in_sizes, int n_in,
                              void* d_out, int out_size)
{
    const float* x     = (const float*)d_in[0];
    const int*   ei    = (const int*)  d_in[1];
    const float* w_l1  = (const float*)d_in[2];
    const float* b1    = (const float*)d_in[3];
    const float* w_r1  = (const float*)d_in[4];
    const float* bn1_g = (const float*)d_in[5];
    const float* bn1_b = (const float*)d_in[6];
    const float* bn1_m = (const float*)d_in[7];
    const float* bn1_v = (const float*)d_in[8];
    const float* w_l2  = (const float*)d_in[9];
    const float* b2    = (const float*)d_in[10];
    const float* w_r2  = (const float*)d_in[11];
    const float* bn2_g = (const float*)d_in[12];
    const float* bn2_b = (const float*)d_in[13];
    const float* bn2_m = (const float*)d_in[14];
    const float* bn2_v = (const float*)d_in[15];
    const float* w_l3  = (const float*)d_in[16];
    const float* b3    = (const float*)d_in[17];
    const float* w_r3  = (const float*)d_in[18];
    float* out = (float*)d_out;

    const int N = in_sizes[0] / DK;
    const int E = in_sizes[1] / 2;
    const int O = out_size / N;   // 256

    float *xt, *agg, *h1, *h2, *wt;
    cudaGetSymbolAddress((void**)&xt,  g_xt);
    cudaGetSymbolAddress((void**)&agg, g_agg);
    cudaGetSymbolAddress((void**)&h1,  g_h1);
    cudaGetSymbolAddress((void**)&h2,  g_h2);
    cudaGetSymbolAddress((void**)&wt,  g_wt);
    float* wlt1 = wt;
    float* wrt1 = wt + 512 * 512;
    float* wlt2 = wt + 2 * 512 * 512;
    float* wrt2 = wt + 3 * 512 * 512;
    float* wlt3 = wt + 4 * 512 * 512;
    float* wrt3 = wt + 4 * 512 * 512 + 256 * 512;

    cudaFuncSetAttribute(k_gemm_mma, cudaFuncAttributeMaxDynamicSharedMemorySize, GSMEM);

    // CSR build
    k_zero_deg<<<(N + 255) / 256, 256>>>(N);
    k_deg     <<<(E + 255) / 256, 256>>>(ei, E);
    k_scan    <<<1, 1024>>>(N);
    k_fill    <<<(E + 255) / 256, 256>>>(ei, E);

    // tf32 pre-rounding: x copy + all weight transposes in one launch
    k_round<<<(N * DK / 4 + 255) / 256, 256>>>(x, xt, N * DK / 4);
    TP6 tps = {{ {w_l1, wlt1, 512}, {w_r1, wrt1, 512},
                 {w_l2, wlt2, 512}, {w_r2, wrt2, 512},
                 {w_l3, wlt3, 256}, {w_r3, wrt3, 256} }};
    k_transpose_all<<<dim3(16, 16, 6), dim3(32, 8)>>>(tps);

    const int mt = (N + 127) / 128;
    dim3 gH(mt, 512 / 128);
    dim3 gO(mt, O / 128);

    // Layer 1
    k_aggregate<<<N, 128>>>(x, agg, N);
    k_gemm_mma<<<gH, 256, GSMEM>>>(agg, xt, wlt1, wrt1, b1,
                                   bn1_g, bn1_b, bn1_m, bn1_v, h1, N, 512, 1);
    // Layer 2
    k_aggregate<<<N, 128>>>(h1, agg, N);
    k_gemm_mma<<<gH, 256, GSMEM>>>(agg, h1, wlt2, wrt2, b2,
                                   bn2_g, bn2_b, bn2_m, bn2_v, h2, N, 512, 1);
    // Layer 3 (no BN/ReLU)
    k_aggregate<<<N, 128>>>(h2, agg, N);
    k_gemm_mma<<<gO, 256, GSMEM>>>(agg, h2, wlt3, wrt3, b3,
                                   b3, b3, b3, b3, out, N, O, 0);
}